// round 9
// baseline (speedup 1.0000x reference)
#include <cuda_runtime.h>

// YOLO postprocess, single fused persistent kernel.
// x: (1, 84, 8400) f32 channel-major; out: (8400, 5) f32.
//
// Phases (grid-wide software barriers between):
//   A: filter score>0.5, warp-aggregated compaction into g_keys
//   B1: rank-by-counting (8 chunks per slot, atomicAdd partial counts)
//   B2: scatter boxes/scores/areas by rank
//   C: sparse IoU suppression edges (64x64 triangle tiles, grid-stride)
//   D: (block 0 only) exact greedy via fixed-point propagation + output + reset
//
// Greedy NMS == unique fixed point of:
//   j SUP  iff exists edge (i,j), i<j, i KEEP
//   j KEEP iff every edge (i,j) has i SUP
// Each round the minimum-index unknown row settles => guaranteed convergence.
//
// Co-residency: 120 blocks, 1024 threads, 160KB dynamic smem => 1 block/SM on
// 148-SM sm_100a, all blocks resident => spin barriers cannot deadlock.

#define N_IN   8400
#define NSORT  8192
#define NB     120
#define NT     1024
#define FULLW  0xffffffffu
#define ECAP   (1 << 20)
#define ESM    40960          // edges cached in smem (160 KB)
#define NB32   256            // 8192 bits / 32
#define DSMEM  (ESM * 4)

// ---------------- global scratch (zero at rest; reset at kernel end) ------
__device__ int      g_cnt;
__device__ int      g_ecnt;
__device__ unsigned g_bar;
__device__ __align__(16) unsigned long long g_keys[NSORT];
__device__ int      g_rank[NSORT];
__device__ __align__(16) float4 g_boxes[NSORT];
__device__ float    g_score[NSORT];
__device__ float    g_area[NSORT];
__device__ unsigned g_edges[ECAP];

extern "C" __global__ void __launch_bounds__(NT, 1)
fused_nms_kernel(const float* __restrict__ x, float* __restrict__ out)
{
    extern __shared__ unsigned dynbuf[];          // phase C: ebuf; phase D: edge cache
    __shared__ float4 cb[64];
    __shared__ float  ca[64];
    __shared__ int ec, gbase;
    __shared__ unsigned keepb[NB32], supb[NB32], nsup[NB32], unkp[NB32];
    __shared__ int notdone;

    const int tid  = threadIdx.x;
    const int bid  = blockIdx.x;
    const int gtid = bid * NT + tid;
    const int lane = tid & 31;

    auto grid_barrier = [&](unsigned target) {
        __syncthreads();
        __threadfence();
        if (tid == 0) {
            atomicAdd(&g_bar, 1u);
            while (atomicAdd(&g_bar, 0u) < target) { }
        }
        __syncthreads();
    };

    // ---- Phase A: zero ranks; filter + compact ----------------------------
    for (int s = gtid; s < NSORT; s += NB * NT) g_rank[s] = 0;
    {
        int n = gtid;                              // NB*NT > N_IN: single shot
        float s = (n < N_IN) ? x[4 * N_IN + n] : 0.f;
        bool pass = (s > 0.5f);
        unsigned m = __ballot_sync(FULLW, pass);
        if (m) {
            int leader = __ffs(m) - 1;
            int base = 0;
            if (lane == leader) base = atomicAdd(&g_cnt, __popc(m));
            base = __shfl_sync(FULLW, base, leader);
            if (pass) {
                int slot = base + __popc(m & ((1u << lane) - 1));
                if (slot < NSORT) {
                    unsigned sb = __float_as_uint(s);
                    g_keys[slot] = ((unsigned long long)(~sb) << 32) | (unsigned)n;
                }
            }
        }
    }
    grid_barrier(NB);

    const int M = min(__ldcg(&g_cnt), NSORT);

    // ---- Phase B1: chunked rank counting ----------------------------------
    // key = (~score_bits)<<32 | idx : ascending == descending score, stable.
    // item = c*M + s : adjacent threads share chunk c (broadcast streaming).
    {
        const int CH = 8;
        const int chlen = (M + CH - 1) / CH;
        const int total = M * CH;
        for (int item = gtid; item < total; item += NB * NT) {
            int c = item / M;
            int s = item - c * M;
            unsigned long long mykey = g_keys[s];
            int lo = c * chlen;
            int hi = min(lo + chlen, M);
            int cnt = 0;
            int k = lo;
            for (; k + 4 <= hi; k += 4) {
                cnt += (g_keys[k]     < mykey) + (g_keys[k + 1] < mykey)
                     + (g_keys[k + 2] < mykey) + (g_keys[k + 3] < mykey);
            }
            for (; k < hi; k++) cnt += (g_keys[k] < mykey);
            if (cnt) atomicAdd(&g_rank[s], cnt);
        }
    }
    grid_barrier(2 * NB);

    // ---- Phase B2: scatter by rank ----------------------------------------
    for (int s = gtid; s < M; s += NB * NT) {
        unsigned long long key = g_keys[s];
        int r = __ldcg(&g_rank[s]);
        int idx = (int)(unsigned)key;
        float X1 = x[idx];
        float Y1 = x[N_IN + idx];
        float X2 = x[2 * N_IN + idx];
        float Y2 = x[3 * N_IN + idx];
        g_boxes[r] = make_float4(X1, Y1, X2, Y2);
        g_score[r] = __uint_as_float(~(unsigned)(key >> 32));
        g_area[r]  = (X2 - X1) * (Y2 - Y1);
    }
    grid_barrier(3 * NB);

    // ---- Phase C: sparse suppression edges (64x64 triangle tiles) ---------
    // IoU > 0.5 <=> 3*inter > area_i + area_j + 1e-9 (denominator always > 0).
    {
        const int nct  = (M + 63) >> 6;
        const int ntri = nct * (nct + 1) / 2;
        unsigned* ebuf = dynbuf;
        for (int tile = bid; tile < ntri; tile += NB) {
            int tx = (int)((sqrtf(8.0f * (float)tile + 1.0f) - 1.0f) * 0.5f);
            while ((tx + 1) * (tx + 2) / 2 <= tile) tx++;
            while (tx * (tx + 1) / 2 > tile) tx--;
            int ty = tile - tx * (tx + 1) / 2;
            int j0 = tx << 6, i0 = ty << 6;

            if (tid == 0) ec = 0;
            if (tid < 64) {
                int jg = j0 + tid;
                if (jg < M) { cb[tid] = g_boxes[jg]; ca[tid] = g_area[jg]; }
                else        { cb[tid] = make_float4(0, 0, 0, 0); ca[tid] = 1e30f; }
            }
            __syncthreads();

            int row = tid >> 4, sub = tid & 15;
            int i = i0 + row;
            if (i < M) {
                float4 b  = g_boxes[i];
                float  sA = g_area[i] + 1e-9f;
                int cbase = sub << 2;
#pragma unroll
                for (int cc = 0; cc < 4; cc++) {
                    int c = cbase + cc;
                    int j = j0 + c;
                    if (j > i && j < M) {
                        float4 q = cb[c];
                        float iw = fminf(b.z, q.z) - fmaxf(b.x, q.x);
                        float ih = fminf(b.w, q.w) - fmaxf(b.y, q.y);
                        float inter = fmaxf(iw, 0.f) * fmaxf(ih, 0.f);
                        if (3.0f * inter > sA + ca[c]) {
                            int p = atomicAdd(&ec, 1);
                            ebuf[p] = ((unsigned)i << 13) | (unsigned)j;
                        }
                    }
                }
            }
            __syncthreads();
            if (tid == 0 && ec > 0) gbase = atomicAdd(&g_ecnt, ec);
            __syncthreads();
            for (int p = tid; p < ec; p += NT) {
                int gp = gbase + p;
                if (gp < ECAP) g_edges[gp] = ebuf[p];
            }
            __syncthreads();
        }
    }

    // ---- final barrier: non-zero blocks arrive and exit -------------------
    __syncthreads();
    __threadfence();
    if (tid == 0) atomicAdd(&g_bar, 1u);
    if (bid != 0) return;
    if (tid == 0) { while (atomicAdd(&g_bar, 0u) < 4u * NB) { } }
    __syncthreads();

    // ---- Phase D (block 0): fixed-point greedy + output + reset -----------
    {
        unsigned* se = dynbuf;
        int E = min(__ldcg(&g_ecnt), ECAP);
        const int Es = min(E, ESM);

        for (int e = tid; e < Es; e += NT) se[e] = g_edges[e];
        if (tid < NB32) { keepb[tid] = 0u; supb[tid] = 0u; }
        __syncthreads();

        for (int round = 0; round < NSORT; round++) {
            if (tid < NB32) { nsup[tid] = 0u; unkp[tid] = 0u; }
            if (tid == 0) notdone = 0;
            __syncthreads();

            for (int e = tid; e < E; e += NT) {
                unsigned ed = (e < ESM) ? se[e] : g_edges[e];
                int i = (int)(ed >> 13), j = (int)(ed & 8191u);
                unsigned jset = (keepb[j >> 5] | supb[j >> 5]) >> (j & 31);
                if (jset & 1u) continue;                      // j settled
                if ((keepb[i >> 5] >> (i & 31)) & 1u)
                    atomicOr(&nsup[j >> 5], 1u << (j & 31));  // KEEP pred
                else if (!((supb[i >> 5] >> (i & 31)) & 1u))
                    atomicOr(&unkp[j >> 5], 1u << (j & 31));  // UNKNOWN pred
            }
            __syncthreads();

            if (tid < NB32) {
                int base = tid << 5;
                unsigned valid = (base + 32 <= M) ? 0xffffffffu
                               : (base >= M ? 0u : ((1u << (M - base)) - 1u));
                unsigned unk = ~(keepb[tid] | supb[tid]) & valid;
                if (unk) {
                    unsigned ns = nsup[tid] & unk;
                    unsigned nk = unk & ~nsup[tid] & ~unkp[tid];
                    supb[tid]  |= ns;
                    keepb[tid] |= nk;
                    if (unk & ~(ns | nk)) notdone = 1;        // benign race
                }
            }
            __syncthreads();
            if (!notdone) break;
        }

        // fused masked output write
        for (int r = tid; r < N_IN; r += NT) {
            if (r < M) {
                float m = (float)((keepb[r >> 5] >> (r & 31)) & 1u);
                float4 b = g_boxes[r];
                out[r * 5 + 0] = b.x * m;
                out[r * 5 + 1] = b.y * m;
                out[r * 5 + 2] = b.z * m;
                out[r * 5 + 3] = b.w * m;
                out[r * 5 + 4] = g_score[r] * m;
            } else {
                out[r * 5 + 0] = 0.f;
                out[r * 5 + 1] = 0.f;
                out[r * 5 + 2] = 0.f;
                out[r * 5 + 3] = 0.f;
                out[r * 5 + 4] = 0.f;
            }
        }

        // restore zero-invariants for next launch / graph replay
        __syncthreads();
        if (tid == 0) { g_cnt = 0; g_ecnt = 0; g_bar = 0u; }
    }
}

// ---------------- launcher ----------------
extern "C" void kernel_launch(void* const* d_in, const int* in_sizes, int n_in,
                              void* d_out, int out_size)
{
    (void)in_sizes; (void)n_in; (void)out_size;
    const float* x = (const float*)d_in[0];
    float* out = (float*)d_out;

    static bool init_done = false;
    if (!init_done) {
        cudaFuncSetAttribute(fused_nms_kernel,
                             cudaFuncAttributeMaxDynamicSharedMemorySize, DSMEM);
        init_done = true;
    }

    fused_nms_kernel<<<NB, NT, DSMEM>>>(x, out);
}

// round 10
// speedup vs baseline: 1.3504x; 1.3504x over previous
#include <cuda_runtime.h>

// YOLO postprocess: filter(score>0.5) -> sort desc -> greedy NMS(IoU>0.5) -> masked rows.
// x: (1, 84, 8400) f32 channel-major; out: (8400, 5) f32.
//
//   K0 filter (warp-aggregated compaction)
//   K1 rank-by-counting sort + gather (smem tiles, chip-parallel)
//   K2 sparse suppression edge list (64x64 tiles, upper triangle)
//   K3 exact greedy fixed-point with live-edge ping-pong compaction + reset
//   K4 masked output write (reads g_M, not g_cnt)
//
// Greedy NMS == unique fixed point of:
//   j SUP  iff exists edge (i,j), i<j, i KEEP
//   j KEEP iff every edge (i,j) has i SUP
// Each round the minimum-index unknown row settles => guaranteed convergence.
// An edge is LIVE only while both endpoints are unknown; live edges are
// compacted into the opposite smem buffer each round.

#define N_IN   8400
#define NSORT  8192
#define FULLW  0xffffffffu
#define ECAP   (1 << 20)      // edge capacity (4 MB scratch; ~25k expected)
#define EBUF   24576          // edges per ping-pong smem buffer (96 KB each)
#define NB32   256            // 8192 bits / 32

// ---------------- global scratch ----------------
__device__ int    g_cnt;      // zero at rest (reset by K3)
__device__ int    g_ecnt;     // zero at rest (reset by K3)
__device__ int    g_M;        // published by K3 for K4
__device__ unsigned long long g_keys[NSORT];
__device__ __align__(16) float4 g_boxes[NSORT];
__device__ float  g_score[NSORT];
__device__ float  g_area[NSORT];
__device__ unsigned g_keepw32[NB32];
__device__ unsigned g_edges[ECAP];

// ---------------- K0: filter + compact (order canonicalized by K1) --------
extern "C" __global__ void __launch_bounds__(256)
k0_filter_kernel(const float* __restrict__ x)
{
    const int n = blockIdx.x * 256 + threadIdx.x;
    bool pass = false;
    float s = 0.f;
    if (n < N_IN) {
        s = x[4 * N_IN + n];
        pass = (s > 0.5f);
    }
    unsigned m = __ballot_sync(FULLW, pass);
    if (!m) return;
    int lane = threadIdx.x & 31;
    int leader = __ffs(m) - 1;
    int base = 0;
    if (lane == leader) base = atomicAdd(&g_cnt, __popc(m));
    base = __shfl_sync(FULLW, base, leader);
    if (pass) {
        int slot = base + __popc(m & ((1u << lane) - 1));
        if (slot < NSORT) {
            unsigned sb = __float_as_uint(s);
            g_keys[slot] = ((unsigned long long)(~sb) << 32) | (unsigned)n;
        }
    }
}

// ---------------- K1: rank-by-counting sort + gather ----------------------
// keys unique (idx in low bits) => rank is an exact permutation.
// key = (~score_bits)<<32 | idx : ascending == descending score, stable ties.
extern "C" __global__ void __launch_bounds__(64)
k1_rank_kernel(const float* __restrict__ x)
{
    __shared__ unsigned long long tile[64];
    const int M = min(g_cnt, NSORT);
    if ((int)(blockIdx.x * 64) >= M) return;          // uniform block early-exit

    const int t = blockIdx.x * 64 + threadIdx.x;
    unsigned long long mykey = (t < M) ? g_keys[t] : ~0ULL;
    int rank = 0;
    for (int base = 0; base < M; base += 64) {
        int c = base + threadIdx.x;
        tile[threadIdx.x] = (c < M) ? g_keys[c] : ~0ULL;  // sentinel never counts
        __syncthreads();
#pragma unroll 16
        for (int j = 0; j < 64; j++)
            rank += (tile[j] < mykey);
        __syncthreads();
    }

    if (t < M) {
        int idx = (int)(unsigned)mykey;
        float X1 = x[idx];
        float Y1 = x[N_IN + idx];
        float X2 = x[2 * N_IN + idx];
        float Y2 = x[3 * N_IN + idx];
        g_boxes[rank] = make_float4(X1, Y1, X2, Y2);
        g_score[rank] = __uint_as_float(~(unsigned)(mykey >> 32));
        g_area[rank]  = (X2 - X1) * (Y2 - Y1);
    }
}

// ---------------- K2: sparse suppression edges (64x64 tiles) --------------
// Edge (i, j), i<j, packed (i<<13)|j, when IoU>0.5:
//   IoU > 0.5 <=> 3*inter > area_i + area_j + 1e-9 (denominator always > 0).
extern "C" __global__ void __launch_bounds__(64)
k2_edges_kernel()
{
    const int bx = blockIdx.x, by = blockIdx.y;
    if (bx < by) return;
    const int M = min(g_cnt, NSORT);
    const int nct = (M + 63) >> 6;
    if (by >= nct || bx >= nct) return;

    __shared__ float4 cb[64];
    __shared__ float  ca[64];
    __shared__ unsigned ebuf[4096];     // worst case: full 64x64 tile
    __shared__ int ec, gbase;
    const int t  = threadIdx.x;
    if (t == 0) ec = 0;
    const int j0 = bx << 6;
    cb[t] = g_boxes[j0 + t];
    ca[t] = g_area[j0 + t];
    __syncthreads();

    const int i = (by << 6) + t;
    if (i < M) {
        const float4 b  = g_boxes[i];
        const float  sA = g_area[i] + 1e-9f;
        const int    nc = min(64, M - j0);
        const int    c0 = (bx == by) ? (t + 1) : 0;   // strict upper triangle
        for (int c = c0; c < nc; c++) {
            float4 q = cb[c];
            float iw = fminf(b.z, q.z) - fmaxf(b.x, q.x);
            float ih = fminf(b.w, q.w) - fmaxf(b.y, q.y);
            float inter = fmaxf(iw, 0.f) * fmaxf(ih, 0.f);
            if (3.0f * inter > sA + ca[c]) {
                int p = atomicAdd(&ec, 1);
                ebuf[p] = ((unsigned)i << 13) | (unsigned)(j0 + c);
            }
        }
    }
    __syncthreads();
    if (t == 0 && ec > 0) gbase = atomicAdd(&g_ecnt, ec);
    __syncthreads();
    for (int p = t; p < ec; p += 64) {
        int gp = gbase + p;
        if (gp < ECAP) g_edges[gp] = ebuf[p];
    }
}

// ---------------- K3: fixed-point with live-edge compaction ---------------
#define K3_SMEM (2 * EBUF * 4)     // 192 KB ping-pong edge buffers

extern "C" __global__ void __launch_bounds__(1024, 1)
k3_fixed_kernel()
{
    extern __shared__ unsigned se[];                  // [2][EBUF]
    __shared__ unsigned keepb[NB32], supb[NB32], nsup[NB32], unkp[NB32];
    __shared__ int notdone, livecnt;
    const int M   = min(g_cnt, NSORT);
    const int tid = threadIdx.x, lane = tid & 31;
    int E = g_ecnt; if (E > ECAP) E = ECAP;
    const int Eover = (E > EBUF) ? (E - EBUF) : 0;    // stays in global, uncompacted

    unsigned* cur = se;
    unsigned* nxt = se + EBUF;
    int curN = min(E, EBUF);

    for (int e = tid; e < curN; e += 1024) cur[e] = g_edges[e];
    if (tid < NB32) { keepb[tid] = 0u; supb[tid] = 0u; }
    __syncthreads();

    for (int round = 0; round < NSORT; round++) {
        if (tid < NB32) { nsup[tid] = 0u; unkp[tid] = 0u; }
        if (tid == 0) { notdone = 0; livecnt = 0; }
        __syncthreads();

        // classify an edge; returns live (both endpoints unknown)
        auto classify = [&](unsigned ed) -> bool {
            int i = (int)(ed >> 13), j = (int)(ed & 8191u);
            unsigned jset = (keepb[j >> 5] | supb[j >> 5]) >> (j & 31);
            if (jset & 1u) return false;                      // j settled
            if ((keepb[i >> 5] >> (i & 31)) & 1u) {
                atomicOr(&nsup[j >> 5], 1u << (j & 31));      // KEEP pred -> SUP
                return false;
            }
            if ((supb[i >> 5] >> (i & 31)) & 1u) return false; // vacuous edge
            atomicOr(&unkp[j >> 5], 1u << (j & 31));          // UNKNOWN pred
            return true;
        };

        // smem edges: classify + warp-aggregated compaction into nxt
        for (int e0 = 0; e0 < curN; e0 += 1024) {
            int e = e0 + tid;
            bool act = (e < curN);
            unsigned ed = act ? cur[e] : 0u;
            bool live = act && classify(ed);
            unsigned m = __ballot_sync(FULLW, live);
            if (m) {
                int leader = __ffs(m) - 1;
                int base = 0;
                if (lane == leader) base = atomicAdd(&livecnt, __popc(m));
                base = __shfl_sync(FULLW, base, leader);
                if (live) nxt[base + __popc(m & ((1u << lane) - 1))] = ed;
            }
        }
        // overflow edges: classify only (never compacted)
        for (int e = tid; e < Eover; e += 1024) classify(g_edges[EBUF + e]);
        __syncthreads();

        if (tid < NB32) {
            int base = tid << 5;
            unsigned valid = (base + 32 <= M) ? 0xffffffffu
                           : (base >= M ? 0u : ((1u << (M - base)) - 1u));
            unsigned unk = ~(keepb[tid] | supb[tid]) & valid;
            if (unk) {
                unsigned ns = nsup[tid] & unk;
                unsigned nk = unk & ~nsup[tid] & ~unkp[tid];
                supb[tid]  |= ns;
                keepb[tid] |= nk;
                if (unk & ~(ns | nk)) notdone = 1;            // benign race
            }
        }
        __syncthreads();
        if (!notdone) break;
        curN = livecnt;
        unsigned* tmp = cur; cur = nxt; nxt = tmp;
        __syncthreads();     // livecnt read complete before next-round reset
    }

    if (tid < NB32) g_keepw32[tid] = keepb[tid];
    // publish M for K4; restore zero-invariants (replaces memset nodes)
    if (tid == 0) { g_M = M; g_cnt = 0; g_ecnt = 0; }
}

// ---------------- K4: masked output write (reads g_M) ----------------
extern "C" __global__ void __launch_bounds__(256)
k4_out_kernel(float* __restrict__ out)
{
    const int r = blockIdx.x * 256 + threadIdx.x;
    if (r >= N_IN) return;
    const int M = g_M;
    if (r < M) {
        float m = (float)((g_keepw32[r >> 5] >> (r & 31)) & 1u);
        float4 b = g_boxes[r];
        out[r * 5 + 0] = b.x * m;
        out[r * 5 + 1] = b.y * m;
        out[r * 5 + 2] = b.z * m;
        out[r * 5 + 3] = b.w * m;
        out[r * 5 + 4] = g_score[r] * m;
    } else {
        out[r * 5 + 0] = 0.f;
        out[r * 5 + 1] = 0.f;
        out[r * 5 + 2] = 0.f;
        out[r * 5 + 3] = 0.f;
        out[r * 5 + 4] = 0.f;
    }
}

// ---------------- launcher ----------------
extern "C" void kernel_launch(void* const* d_in, const int* in_sizes, int n_in,
                              void* d_out, int out_size)
{
    (void)in_sizes; (void)n_in; (void)out_size;
    const float* x = (const float*)d_in[0];
    float* out = (float*)d_out;

    static bool init_done = false;
    if (!init_done) {
        cudaFuncSetAttribute(k3_fixed_kernel,
                             cudaFuncAttributeMaxDynamicSharedMemorySize, K3_SMEM);
        init_done = true;
    }

    k0_filter_kernel<<<(N_IN + 255) / 256, 256>>>(x);
    k1_rank_kernel<<<NSORT / 64, 64>>>(x);
    k2_edges_kernel<<<dim3(NSORT / 64, NSORT / 64), 64>>>();
    k3_fixed_kernel<<<1, 1024, K3_SMEM>>>();
    k4_out_kernel<<<(N_IN + 255) / 256, 256>>>(out);
}

// round 11
// speedup vs baseline: 1.7372x; 1.2864x over previous
#include <cuda_runtime.h>

// YOLO postprocess: filter(score>0.5) -> sort desc -> greedy NMS(IoU>0.5) -> masked rows.
// x: (1, 84, 8400) f32 channel-major; out: (8400, 5) f32.
//
//   K0 filter (warp-aggregated compaction)
//   K1 rank-by-counting sort + gather (4 threads/key, smem tiles)
//   K2 sparse suppression edge list (64x64 tiles, 4 threads/row, triangle grid)
//   K3 exact greedy fixed-point with live-edge ping-pong compaction + reset
//   K4 masked output write (reads g_M, not g_cnt)
//
// Greedy NMS == unique fixed point of:
//   j SUP  iff exists edge (i,j), i<j, i KEEP
//   j KEEP iff every edge (i,j) has i SUP
// Each round the minimum-index unknown row settles => guaranteed convergence.

#define N_IN   8400
#define NSORT  8192
#define FULLW  0xffffffffu
#define ECAP   (1 << 20)      // edge capacity (4 MB scratch; ~25k expected)
#define EBUF   24576          // edges per ping-pong smem buffer (96 KB each)
#define NB32   256            // 8192 bits / 32

// ---------------- global scratch ----------------
__device__ int    g_cnt;      // zero at rest (reset by K3)
__device__ int    g_ecnt;     // zero at rest (reset by K3)
__device__ int    g_M;        // published by K3 for K4
__device__ unsigned long long g_keys[NSORT];
__device__ __align__(16) float4 g_boxes[NSORT];
__device__ float  g_score[NSORT];
__device__ float  g_area[NSORT];
__device__ unsigned g_keepw32[NB32];
__device__ unsigned g_edges[ECAP];

// ---------------- K0: filter + compact (order canonicalized by K1) --------
extern "C" __global__ void __launch_bounds__(256)
k0_filter_kernel(const float* __restrict__ x)
{
    const int n = blockIdx.x * 256 + threadIdx.x;
    bool pass = false;
    float s = 0.f;
    if (n < N_IN) {
        s = x[4 * N_IN + n];
        pass = (s > 0.5f);
    }
    unsigned m = __ballot_sync(FULLW, pass);
    if (!m) return;
    int lane = threadIdx.x & 31;
    int leader = __ffs(m) - 1;
    int base = 0;
    if (lane == leader) base = atomicAdd(&g_cnt, __popc(m));
    base = __shfl_sync(FULLW, base, leader);
    if (pass) {
        int slot = base + __popc(m & ((1u << lane) - 1));
        if (slot < NSORT) {
            unsigned sb = __float_as_uint(s);
            g_keys[slot] = ((unsigned long long)(~sb) << 32) | (unsigned)n;
        }
    }
}

// ---------------- K1: rank-by-counting sort + gather (4 threads/key) ------
// keys unique (idx in low bits) => rank is an exact permutation.
// key = (~score_bits)<<32 | idx : ascending == descending score, stable ties.
// 256 threads: key_l = tid&63, sub = tid>>6; each sub counts its 64-entry
// quarter of every 256-key tile; partial ranks reduced in smem.
extern "C" __global__ void __launch_bounds__(256)
k1_rank_kernel(const float* __restrict__ x)
{
    __shared__ unsigned long long tile[256];
    __shared__ int srank[64][4];
    const int M = min(g_cnt, NSORT);
    if ((int)(blockIdx.x * 64) >= M) return;          // uniform block early-exit

    const int tid   = threadIdx.x;
    const int key_l = tid & 63;
    const int sub   = tid >> 6;
    const int kslot = blockIdx.x * 64 + key_l;
    const unsigned long long mykey = (kslot < M) ? g_keys[kslot] : ~0ULL;

    int cnt = 0;
    for (int base = 0; base < M; base += 256) {
        int c = base + tid;
        tile[tid] = (c < M) ? g_keys[c] : ~0ULL;      // sentinel never counts
        __syncthreads();
        const unsigned long long* tp = tile + (sub << 6);   // warp-broadcast reads
#pragma unroll 16
        for (int j = 0; j < 64; j++)
            cnt += (tp[j] < mykey);
        __syncthreads();
    }
    srank[key_l][sub] = cnt;
    __syncthreads();

    if (sub == 0 && kslot < M) {
        int rank = srank[key_l][0] + srank[key_l][1]
                 + srank[key_l][2] + srank[key_l][3];
        int idx = (int)(unsigned)mykey;
        float X1 = x[idx];
        float Y1 = x[N_IN + idx];
        float X2 = x[2 * N_IN + idx];
        float Y2 = x[3 * N_IN + idx];
        g_boxes[rank] = make_float4(X1, Y1, X2, Y2);
        g_score[rank] = __uint_as_float(~(unsigned)(mykey >> 32));
        g_area[rank]  = (X2 - X1) * (Y2 - Y1);
    }
}

// ---------------- K2: sparse edges (64x64 tiles, 4 threads/row) -----------
// Triangle-linear grid (ty <= tx); edge (i,j), i<j, packed (i<<13)|j when
//   IoU > 0.5 <=> 3*inter > area_i + area_j + 1e-9 (denominator always > 0).
#define NCT64   (NSORT / 64)                     // 128
#define K2_GRID (NCT64 * (NCT64 + 1) / 2)        // 8256

extern "C" __global__ void __launch_bounds__(256)
k2_edges_kernel()
{
    // linear -> (ty <= tx) triangle decode
    const int L = blockIdx.x;
    int tx = (int)((sqrtf(8.0f * (float)L + 1.0f) - 1.0f) * 0.5f);
    while ((tx + 1) * (tx + 2) / 2 <= L) tx++;
    while (tx * (tx + 1) / 2 > L) tx--;
    const int ty = L - tx * (tx + 1) / 2;

    const int M = min(g_cnt, NSORT);
    const int nct = (M + 63) >> 6;
    if (ty >= nct || tx >= nct) return;

    __shared__ float4 cb[64];
    __shared__ float  ca[64];
    __shared__ unsigned ebuf[4096];     // worst case: full 64x64 tile
    __shared__ int ec, gbase;
    const int t  = threadIdx.x;
    if (t == 0) ec = 0;
    const int j0 = tx << 6;
    if (t < 64) {
        int jg = j0 + t;
        if (jg < M) { cb[t] = g_boxes[jg]; ca[t] = g_area[jg]; }
        else        { cb[t] = make_float4(0, 0, 0, 0); ca[t] = 1e30f; }
    }
    __syncthreads();

    const int row = t >> 2, sub = t & 3;
    const int i   = (ty << 6) + row;
    if (i < M) {
        const float4 b  = g_boxes[i];
        const float  sA = g_area[i] + 1e-9f;
        const int    c1 = min((sub << 4) + 16, M - j0);
#pragma unroll 4
        for (int c = sub << 4; c < c1; c++) {
            int j = j0 + c;
            if (j > i) {
                float4 q = cb[c];
                float iw = fminf(b.z, q.z) - fmaxf(b.x, q.x);
                float ih = fminf(b.w, q.w) - fmaxf(b.y, q.y);
                float inter = fmaxf(iw, 0.f) * fmaxf(ih, 0.f);
                if (3.0f * inter > sA + ca[c]) {
                    int p = atomicAdd(&ec, 1);
                    ebuf[p] = ((unsigned)i << 13) | (unsigned)j;
                }
            }
        }
    }
    __syncthreads();
    if (t == 0 && ec > 0) gbase = atomicAdd(&g_ecnt, ec);
    __syncthreads();
    for (int p = t; p < ec; p += 256) {
        int gp = gbase + p;
        if (gp < ECAP) g_edges[gp] = ebuf[p];
    }
}

// ---------------- K3: fixed-point with live-edge compaction ---------------
#define K3_SMEM (2 * EBUF * 4)     // 192 KB ping-pong edge buffers

extern "C" __global__ void __launch_bounds__(1024, 1)
k3_fixed_kernel()
{
    extern __shared__ unsigned se[];                  // [2][EBUF]
    __shared__ unsigned keepb[NB32], supb[NB32], nsup[NB32], unkp[NB32];
    __shared__ int notdone, livecnt;
    const int M   = min(g_cnt, NSORT);
    const int tid = threadIdx.x, lane = tid & 31;
    int E = g_ecnt; if (E > ECAP) E = ECAP;
    const int Eover = (E > EBUF) ? (E - EBUF) : 0;    // stays in global, uncompacted

    unsigned* cur = se;
    unsigned* nxt = se + EBUF;
    int curN = min(E, EBUF);

    for (int e = tid; e < curN; e += 1024) cur[e] = g_edges[e];
    if (tid < NB32) { keepb[tid] = 0u; supb[tid] = 0u; }
    __syncthreads();

    for (int round = 0; round < NSORT; round++) {
        if (tid < NB32) { nsup[tid] = 0u; unkp[tid] = 0u; }
        if (tid == 0) { notdone = 0; livecnt = 0; }
        __syncthreads();

        // classify an edge; returns live (both endpoints unknown)
        auto classify = [&](unsigned ed) -> bool {
            int i = (int)(ed >> 13), j = (int)(ed & 8191u);
            unsigned jset = (keepb[j >> 5] | supb[j >> 5]) >> (j & 31);
            if (jset & 1u) return false;                      // j settled
            if ((keepb[i >> 5] >> (i & 31)) & 1u) {
                atomicOr(&nsup[j >> 5], 1u << (j & 31));      // KEEP pred -> SUP
                return false;
            }
            if ((supb[i >> 5] >> (i & 31)) & 1u) return false; // vacuous edge
            atomicOr(&unkp[j >> 5], 1u << (j & 31));          // UNKNOWN pred
            return true;
        };

        // smem edges: classify + warp-aggregated compaction into nxt
        for (int e0 = 0; e0 < curN; e0 += 1024) {
            int e = e0 + tid;
            bool act = (e < curN);
            unsigned ed = act ? cur[e] : 0u;
            bool live = act && classify(ed);
            unsigned m = __ballot_sync(FULLW, live);
            if (m) {
                int leader = __ffs(m) - 1;
                int base = 0;
                if (lane == leader) base = atomicAdd(&livecnt, __popc(m));
                base = __shfl_sync(FULLW, base, leader);
                if (live) nxt[base + __popc(m & ((1u << lane) - 1))] = ed;
            }
        }
        // overflow edges: classify only (never compacted)
        for (int e = tid; e < Eover; e += 1024) classify(g_edges[EBUF + e]);
        __syncthreads();

        if (tid < NB32) {
            int base = tid << 5;
            unsigned valid = (base + 32 <= M) ? 0xffffffffu
                           : (base >= M ? 0u : ((1u << (M - base)) - 1u));
            unsigned unk = ~(keepb[tid] | supb[tid]) & valid;
            if (unk) {
                unsigned ns = nsup[tid] & unk;
                unsigned nk = unk & ~nsup[tid] & ~unkp[tid];
                supb[tid]  |= ns;
                keepb[tid] |= nk;
                if (unk & ~(ns | nk)) notdone = 1;            // benign race
            }
        }
        __syncthreads();
        if (!notdone) break;
        curN = livecnt;
        unsigned* tmp = cur; cur = nxt; nxt = tmp;
        __syncthreads();     // livecnt read complete before next-round reset
    }

    if (tid < NB32) g_keepw32[tid] = keepb[tid];
    // publish M for K4; restore zero-invariants (replaces memset nodes)
    if (tid == 0) { g_M = M; g_cnt = 0; g_ecnt = 0; }
}

// ---------------- K4: masked output write (reads g_M) ----------------
extern "C" __global__ void __launch_bounds__(256)
k4_out_kernel(float* __restrict__ out)
{
    const int r = blockIdx.x * 256 + threadIdx.x;
    if (r >= N_IN) return;
    const int M = g_M;
    if (r < M) {
        float m = (float)((g_keepw32[r >> 5] >> (r & 31)) & 1u);
        float4 b = g_boxes[r];
        out[r * 5 + 0] = b.x * m;
        out[r * 5 + 1] = b.y * m;
        out[r * 5 + 2] = b.z * m;
        out[r * 5 + 3] = b.w * m;
        out[r * 5 + 4] = g_score[r] * m;
    } else {
        out[r * 5 + 0] = 0.f;
        out[r * 5 + 1] = 0.f;
        out[r * 5 + 2] = 0.f;
        out[r * 5 + 3] = 0.f;
        out[r * 5 + 4] = 0.f;
    }
}

// ---------------- launcher ----------------
extern "C" void kernel_launch(void* const* d_in, const int* in_sizes, int n_in,
                              void* d_out, int out_size)
{
    (void)in_sizes; (void)n_in; (void)out_size;
    const float* x = (const float*)d_in[0];
    float* out = (float*)d_out;

    static bool init_done = false;
    if (!init_done) {
        cudaFuncSetAttribute(k3_fixed_kernel,
                             cudaFuncAttributeMaxDynamicSharedMemorySize, K3_SMEM);
        init_done = true;
    }

    k0_filter_kernel<<<(N_IN + 255) / 256, 256>>>(x);
    k1_rank_kernel<<<NSORT / 64, 256>>>(x);
    k2_edges_kernel<<<K2_GRID, 256>>>();
    k3_fixed_kernel<<<1, 1024, K3_SMEM>>>();
    k4_out_kernel<<<(N_IN + 255) / 256, 256>>>(out);
}